// round 11
// baseline (speedup 1.0000x reference)
#include <cuda_runtime.h>
#include <cstring>

// B-spline layer via per-span cubic collapse:
//   u = 61*x, m = floor(u), t = u-m
//   out[b,f] = A0(m,f) + A1 t + A2 t^2 + A3 t^3
// A_c(m,f) = sum_r basis[m][r][c] * cp[m+r][f], bias folded into A0.
// Basis polys: host-built (double precision), passed by value (constant bank).
//
// R11: R10 structure (feature-quarter CTAs, 31.25 KB smem table, 256 thr)
// + ALL 16 x LDGs issued at kernel entry (MLP=16), hidden under the table
// copy + barrier. launch_bounds(256,4): 64-reg budget, no spills.

#define NF    128
#define FQ    32            // features per eval CTA (quarter)
#define NSPAN 61
#define TBP   256           // producer block
#define TBE   256           // eval block
#define RPB   128           // rows per eval CTA
#define RPT   16            // rows per thread (per warp: 16 consecutive rows)
#define UC    4             // rows per eval chunk

#define TAB_ENTRIES (NSPAN * NF)            // 7808
#define QT_ENTRIES  (NSPAN * FQ)            // 1952

struct BasisTab {
    float4 b[NSPAN * 4];    // [m][r] -> (c0,c1,c2,c3) coeffs in t
};

__device__ float4 g_table[TAB_ENTRIES];     // 125 KB staging (L2-hot)

// ---- producer: fold cp + bias with basis polys -> g_table, once ----
__global__ void __launch_bounds__(TBP)
build_table_kernel(const BasisTab bt,
                   const float* __restrict__ cp,
                   const float* __restrict__ bias)
{
    const int idx = blockIdx.x * TBP + threadIdx.x;
    if (idx >= TAB_ENTRIES) return;
    const int m = idx >> 7;                 // warp-uniform -> bt reads are LDC
    const int f = idx & (NF - 1);
    const float c0 = cp[(m + 0) * NF + f];
    const float c1 = cp[(m + 1) * NF + f];
    const float c2 = cp[(m + 2) * NF + f];
    const float c3 = cp[(m + 3) * NF + f];
    const float4 b0 = bt.b[m * 4 + 0];
    const float4 b1 = bt.b[m * 4 + 1];
    const float4 b2 = bt.b[m * 4 + 2];
    const float4 b3 = bt.b[m * 4 + 3];
    float4 A;
    A.x = fmaf(c0, b0.x, fmaf(c1, b1.x, fmaf(c2, b2.x, fmaf(c3, b3.x, bias[f]))));
    A.y = fmaf(c0, b0.y, fmaf(c1, b1.y, fmaf(c2, b2.y, c3 * b3.y)));
    A.z = fmaf(c0, b0.z, fmaf(c1, b1.z, fmaf(c2, b2.z, c3 * b3.z)));
    A.w = fmaf(c0, b0.w, fmaf(c1, b1.w, fmaf(c2, b2.w, c3 * b3.w)));
    g_table[idx] = A;
}

// ---- consumer: copy quarter-table to smem, evaluate ----
template <bool GUARD>
__global__ void __launch_bounds__(TBE, 4)
bspline_eval_kernel(const float* __restrict__ x,
                    float* __restrict__ out,
                    int B)
{
    __shared__ float4 table[QT_ENTRIES];    // [61][32] this CTA's quarter

    const int tid  = threadIdx.x;
    const int q    = blockIdx.x & 3;        // feature quarter
    const int tile = blockIdx.x >> 2;       // row tile
    const int lane = tid & 31;              // local feature 0..31
    const int wrp  = tid >> 5;              // 0..7
    const int fg   = q * FQ + lane;         // global feature

    const int rowBase = tile * RPB + wrp * RPT;
    const float* __restrict__ xp = x + rowBase * NF + fg;
    float* __restrict__ op       = out + rowBase * NF + fg;

    // ---- stage A: front-load ALL 16 x values (MLP = 16) ----
    float xv[RPT];
#pragma unroll
    for (int j = 0; j < RPT; j++) {
        if (!GUARD || rowBase + j < B) xv[j] = xp[j * NF];
    }

    // ---- stage B: copy quarter of the table (coalesced LDG.128, L2-hot);
    //      this + the barrier hides stage A's DRAM round trip ----
    {
        const float4* __restrict__ src = g_table + q * FQ;
#pragma unroll
        for (int it = 0; it < (QT_ENTRIES + TBE - 1) / TBE; it++) {
            const int idx = tid + it * TBE;
            if (idx < QT_ENTRIES) {
                const int m  = idx >> 5;
                const int ff = idx & 31;
                table[idx] = src[m * NF + ff];
            }
        }
    }
    __syncthreads();

    // ---- stage C: eval from registers + smem (conflict-free LDS.128) ----
#pragma unroll
    for (int c = 0; c < RPT / UC; c++) {
        float  t[UC];
        float4 A[UC];
#pragma unroll
        for (int j = 0; j < UC; j++) {
            const float u  = xv[c * UC + j] * 61.0f;
            const float fm = floorf(u);      // x in [0,1) -> m in [0,60]
            t[j] = u - fm;
            A[j] = table[(int)fm * FQ + lane];
        }
#pragma unroll
        for (int j = 0; j < UC; j++) {
            float r = fmaf(A[j].w, t[j], A[j].z);
            r = fmaf(r, t[j], A[j].y);
            r = fmaf(r, t[j], A[j].x);
            const int jj = c * UC + j;
            if (!GUARD || rowBase + jj < B) op[jj * NF] = r;
        }
    }
}

// ---- host-side basis polynomial construction (input-independent) ----
static inline double knotd(int im3) {
    double v = (double)im3;
    if (v < 0.0) v = 0.0;
    if (v > 61.0) v = 61.0;
    return v;
}

static void build_basis(BasisTab* bt)
{
    for (int m = 0; m < NSPAN; m++) {
        double P[4][4];
        memset(P, 0, sizeof(P));
        P[0][0] = 1.0;   // k=0: N_{m+3}^0 = 1 on the span

        for (int k = 1; k <= 3; k++) {
            double Q[4][4];
            memset(Q, 0, sizeof(Q));
            for (int j = 0; j <= k; j++) {
                const int i = m + 3 - k + j;
                const double ti   = knotd(i - 3);
                const double ti1  = knotd(i - 2);
                const double tik  = knotd(i - 3 + k);
                const double tik1 = knotd(i - 2 + k);
                if (j >= 1 && tik != ti) {
                    const double inv = 1.0 / (tik - ti);
                    const double a0  = ((double)m - ti) * inv;
                    for (int c = 0; c < 4; c++) Q[j][c]     += a0  * P[j - 1][c];
                    for (int c = 0; c < 3; c++) Q[j][c + 1] += inv * P[j - 1][c];
                }
                if (j <= k - 1 && tik1 != ti1) {
                    const double inv = 1.0 / (tik1 - ti1);
                    const double b0  = (tik1 - (double)m) * inv;
                    for (int c = 0; c < 4; c++) Q[j][c]     += b0  * P[j][c];
                    for (int c = 0; c < 3; c++) Q[j][c + 1] -= inv * P[j][c];
                }
            }
            memcpy(P, Q, sizeof(P));
        }
        for (int r = 0; r < 4; r++) {
            bt->b[m * 4 + r].x = (float)P[r][0];
            bt->b[m * 4 + r].y = (float)P[r][1];
            bt->b[m * 4 + r].z = (float)P[r][2];
            bt->b[m * 4 + r].w = (float)P[r][3];
        }
    }
}

extern "C" void kernel_launch(void* const* d_in, const int* in_sizes, int n_in,
                              void* d_out, int out_size)
{
    const float* x    = (const float*)d_in[0];
    const float* cp   = (const float*)d_in[1];
    const float* bias = (const float*)d_in[2];
    float* out = (float*)d_out;

    const int B = in_sizes[0] / NF;   // 16384 rows

    static BasisTab bt;
    build_basis(&bt);                 // deterministic per call

    // producer: build the 61x128 coefficient table once
    build_table_kernel<<<(TAB_ENTRIES + TBP - 1) / TBP, TBP>>>(bt, cp, bias);

    // consumer: evaluate (4 feature-quarters x row tiles)
    if ((B % RPB) == 0) {
        const int grid = (B / RPB) * 4;                 // 512 CTAs
        bspline_eval_kernel<false><<<grid, TBE>>>(x, out, B);
    } else {
        const int grid = ((B + RPB - 1) / RPB) * 4;
        bspline_eval_kernel<true><<<grid, TBE>>>(x, out, B);
    }
}